// round 3
// baseline (speedup 1.0000x reference)
#include <cuda_runtime.h>

#define NB 16      // batch
#define NS 512     // seq
#define NH 384     // hidden
#define NL 2000    // max_mel_len
#define NBINS 256
#define H4 (NH/4)  // 96 float4 per row

#define ROWS_PER_BLK 32
#define ITERS 8

// scratch (no allocation allowed in kernel_launch)
__device__ int    g_seg[NB * NL];
__device__ float4 g_comb[NB * H4];   // pemb[pi_b] + eemb[ei_b]

// One block per batch row, 512 threads (one per source token).
__global__ void __launch_bounds__(NS) prep_kernel(
    const float* __restrict__ log_duration,
    const float* __restrict__ pitch,
    const float* __restrict__ energy,
    const float4* __restrict__ pemb,
    const float4* __restrict__ eemb,
    float* __restrict__ out_tail, int write_tail)
{
    const int b    = blockIdx.x;
    const int tid  = threadIdx.x;
    const int warp = tid >> 5;
    const int lane = tid & 31;

    __shared__ int   wsum[16];
    __shared__ float wred[16];
    __shared__ int   s_pidx, s_eidx;

    // duration = max(round(exp(ld) - 1), 0)
    const float ld = log_duration[b * NS + tid];
    const int d = (int)fmaxf(rintf(expf(ld) - 1.0f), 0.0f);

    // ---- inclusive scan over S=512: warp shfl scan + cross-warp ----
    int x = d;
    #pragma unroll
    for (int off = 1; off < 32; off <<= 1) {
        int y = __shfl_up_sync(0xffffffffu, x, off);
        if (lane >= off) x += y;
    }
    if (lane == 31) wsum[warp] = x;
    __syncthreads();
    if (warp == 0 && lane < 16) {
        int v = wsum[lane];
        #pragma unroll
        for (int off = 1; off < 16; off <<= 1) {
            int y = __shfl_up_sync(0x0000ffffu, v, off);
            if (lane >= off) v += y;
        }
        wsum[lane] = v;
    }
    __syncthreads();
    const int cum   = x + (warp ? wsum[warp - 1] : 0);
    const int start = cum - d;
    const int total = wsum[15];

    // ---- pitch / energy means via shfl reductions ----
    float p = pitch[b * NS + tid];
    float e = energy[b * NS + tid];
    #pragma unroll
    for (int off = 16; off > 0; off >>= 1) {
        p += __shfl_xor_sync(0xffffffffu, p, off);
        e += __shfl_xor_sync(0xffffffffu, e, off);
    }
    if (lane == 0) wred[warp] = p;
    __syncthreads();
    if (tid == 0) {
        float s = 0.f;
        #pragma unroll
        for (int i = 0; i < 16; i++) s += wred[i];
        s_pidx = min(max((int)(s * (1.0f / NS)), 0), NBINS - 1);
    }
    __syncthreads();
    if (lane == 0) wred[warp] = e;
    __syncthreads();
    if (tid == 0) {
        float s = 0.f;
        #pragma unroll
        for (int i = 0; i < 16; i++) s += wred[i];
        s_eidx = min(max((int)(s * (1.0f / NS)), 0), NBINS - 1);
        if (write_tail) out_tail[b] = (float)min(total, NL);
    }
    __syncthreads();

    // ---- combined embedding row: comb = pemb[pi] + eemb[ei] ----
    if (tid < H4) {
        float4 pv = pemb[s_pidx * H4 + tid];
        float4 ev = eemb[s_eidx * H4 + tid];
        pv.x += ev.x; pv.y += ev.y; pv.z += ev.z; pv.w += ev.w;
        g_comb[b * H4 + tid] = pv;
    }

    // ---- segment map: init -1, scatter each token's interval ----
    for (int l = tid; l < NL; l += NS) g_seg[b * NL + l] = -1;
    __syncthreads();
    const int end = min(cum, NL);
    for (int l = start; l < end; ++l) g_seg[b * NL + l] = tid;
}

// grid (ceil(NL/32), NB), block (96, 4). Each thread owns column q,
// handles 8 rows (stride 4). All loads front-batched, branchless mask.
__global__ void __launch_bounds__(384) expand_kernel(
    const float4* __restrict__ enc,
    float4* __restrict__ out)
{
    const int q  = threadIdx.x;                      // 0..95
    const int b  = blockIdx.y;                       // 0..15
    const int l0 = blockIdx.x * ROWS_PER_BLK + threadIdx.y;

    const float4 c = g_comb[b * H4 + q];
    const float4* __restrict__ encb = enc + b * (NS * H4);
    float4* __restrict__ outb = out + b * (NL * H4);
    const int* __restrict__ segb = g_seg + b * NL;

    // batch all seg loads (warp-uniform broadcasts)
    int sv[ITERS];
    #pragma unroll
    for (int i = 0; i < ITERS; i++) {
        const int l = min(l0 + i * 4, NL - 1);
        sv[i] = segb[l];
    }

    // batch all enc loads, unconditional (clamped index)
    float4 ev[ITERS];
    #pragma unroll
    for (int i = 0; i < ITERS; i++) {
        ev[i] = __ldg(&encb[max(sv[i], 0) * H4 + q]);
    }

    // masked add + store
    #pragma unroll
    for (int i = 0; i < ITERS; i++) {
        const int l = l0 + i * 4;
        const float m = (sv[i] >= 0) ? 1.0f : 0.0f;
        float4 v;
        v.x = fmaf(m, ev[i].x, c.x);
        v.y = fmaf(m, ev[i].y, c.y);
        v.z = fmaf(m, ev[i].z, c.z);
        v.w = fmaf(m, ev[i].w, c.w);
        if (l < NL) outb[l * H4 + q] = v;
    }
}

extern "C" void kernel_launch(void* const* d_in, const int* in_sizes, int n_in,
                              void* d_out, int out_size)
{
    const float* enc   = (const float*)d_in[0];  // (B,S,H)
    const float* ldur  = (const float*)d_in[1];  // (B,S)
    const float* pitch = (const float*)d_in[2];  // (B,S)
    const float* energ = (const float*)d_in[3];  // (B,S)
    const float* pemb  = (const float*)d_in[4];  // (256,H)
    const float* eemb  = (const float*)d_in[5];  // (256,H)

    float* out = (float*)d_out;
    const int main_elems = NB * NL * NH;
    const int write_tail = (out_size >= main_elems + NB) ? 1 : 0;

    prep_kernel<<<NB, NS>>>(ldur, pitch, energ,
                            (const float4*)pemb, (const float4*)eemb,
                            out + main_elems, write_tail);

    dim3 grid((NL + ROWS_PER_BLK - 1) / ROWS_PER_BLK, NB);
    dim3 block(96, 4);
    expand_kernel<<<grid, block>>>((const float4*)enc, (float4*)out);
}

// round 4
// speedup vs baseline: 1.0259x; 1.0259x over previous
#include <cuda_runtime.h>
#include <cstdint>

#define NB 16      // batch
#define NS 512     // seq
#define NH 384     // hidden
#define NL 2000    // max_mel_len
#define NBINS 256
#define H4 (NH/4)  // 96 float4 per row

#define TR 16                       // tile rows per block (125 blocks exactly)
#define TILE_BYTES (TR * NH * 4)    // 24576

// scratch (no allocation allowed in kernel_launch)
__device__ int    g_seg[NB * NL];
__device__ float4 g_comb[NB * H4];   // pemb[pi_b] + eemb[ei_b]

// One block per batch row, 512 threads (one per source token).
__global__ void __launch_bounds__(NS) prep_kernel(
    const float* __restrict__ log_duration,
    const float* __restrict__ pitch,
    const float* __restrict__ energy,
    const float4* __restrict__ pemb,
    const float4* __restrict__ eemb,
    float* __restrict__ out_tail, int write_tail)
{
    const int b    = blockIdx.x;
    const int tid  = threadIdx.x;
    const int warp = tid >> 5;
    const int lane = tid & 31;

    __shared__ int   wsum[16];
    __shared__ float wred[16];
    __shared__ int   s_pidx, s_eidx;

    // duration = max(round(exp(ld) - 1), 0)
    const float ld = log_duration[b * NS + tid];
    const int d = (int)fmaxf(rintf(expf(ld) - 1.0f), 0.0f);

    // ---- inclusive scan over S=512: warp shfl scan + cross-warp ----
    int x = d;
    #pragma unroll
    for (int off = 1; off < 32; off <<= 1) {
        int y = __shfl_up_sync(0xffffffffu, x, off);
        if (lane >= off) x += y;
    }
    if (lane == 31) wsum[warp] = x;
    __syncthreads();
    if (warp == 0 && lane < 16) {
        int v = wsum[lane];
        #pragma unroll
        for (int off = 1; off < 16; off <<= 1) {
            int y = __shfl_up_sync(0x0000ffffu, v, off);
            if (lane >= off) v += y;
        }
        wsum[lane] = v;
    }
    __syncthreads();
    const int cum   = x + (warp ? wsum[warp - 1] : 0);
    const int start = cum - d;
    const int total = wsum[15];

    // ---- pitch / energy means via shfl reductions ----
    float p = pitch[b * NS + tid];
    float e = energy[b * NS + tid];
    #pragma unroll
    for (int off = 16; off > 0; off >>= 1) {
        p += __shfl_xor_sync(0xffffffffu, p, off);
        e += __shfl_xor_sync(0xffffffffu, e, off);
    }
    if (lane == 0) wred[warp] = p;
    __syncthreads();
    if (tid == 0) {
        float s = 0.f;
        #pragma unroll
        for (int i = 0; i < 16; i++) s += wred[i];
        s_pidx = min(max((int)(s * (1.0f / NS)), 0), NBINS - 1);
    }
    __syncthreads();
    if (lane == 0) wred[warp] = e;
    __syncthreads();
    if (tid == 0) {
        float s = 0.f;
        #pragma unroll
        for (int i = 0; i < 16; i++) s += wred[i];
        s_eidx = min(max((int)(s * (1.0f / NS)), 0), NBINS - 1);
        if (write_tail) out_tail[b] = (float)min(total, NL);
    }
    __syncthreads();

    // ---- combined embedding row: comb = pemb[pi] + eemb[ei] ----
    if (tid < H4) {
        float4 pv = pemb[s_pidx * H4 + tid];
        float4 ev = eemb[s_eidx * H4 + tid];
        pv.x += ev.x; pv.y += ev.y; pv.z += ev.z; pv.w += ev.w;
        g_comb[b * H4 + tid] = pv;
    }

    // ---- segment map: init -1, scatter each token's interval ----
    for (int l = tid; l < NL; l += NS) g_seg[b * NL + l] = -1;
    __syncthreads();
    const int end = min(cum, NL);
    for (int l = start; l < end; ++l) g_seg[b * NL + l] = tid;
}

// grid (NL/TR, NB), block (96, 4). Each thread owns column q and 4
// CONSECUTIVE rows. Tile built in smem, stored via one 1D TMA bulk copy.
__global__ void __launch_bounds__(384) expand_kernel(
    const float4* __restrict__ enc,
    float4* __restrict__ out)
{
    __shared__ __align__(128) float4 tile[TR * H4];   // 24 KB

    const int q  = threadIdx.x;                 // 0..95
    const int yy = threadIdx.y;                 // 0..3
    const int b  = blockIdx.y;                  // 0..15
    const int l0 = blockIdx.x * TR;             // tile base row

    const float4 c = g_comb[b * H4 + q];
    const float4* __restrict__ encb = enc + b * (NS * H4);

    // 4 consecutive seg values in one 16B load (alignment: 8000*b + 64*blk + 16*yy)
    const int4 s4 = *(const int4*)(g_seg + b * NL + l0 + yy * 4);
    const int sv[4] = { s4.x, s4.y, s4.z, s4.w };

    // front-batched unconditional gather loads
    float4 ev[4];
    #pragma unroll
    for (int i = 0; i < 4; i++)
        ev[i] = __ldg(&encb[max(sv[i], 0) * H4 + q]);

    // masked add, write tile rows yy*4 .. yy*4+3
    #pragma unroll
    for (int i = 0; i < 4; i++) {
        const float m = (sv[i] >= 0) ? 1.0f : 0.0f;
        float4 v;
        v.x = fmaf(m, ev[i].x, c.x);
        v.y = fmaf(m, ev[i].y, c.y);
        v.z = fmaf(m, ev[i].z, c.z);
        v.w = fmaf(m, ev[i].w, c.w);
        tile[(yy * 4 + i) * H4 + q] = v;
    }
    __syncthreads();

    // one elected thread bulk-stores the whole tile (contiguous in gmem)
    if (q == 0 && yy == 0) {
        uint32_t saddr;
        asm("{ .reg .u64 t; cvta.to.shared.u64 t, %1; cvt.u32.u64 %0, t; }"
            : "=r"(saddr) : "l"((const void*)tile));
        const float4* gdst = out + (size_t)(b * NL + l0) * H4;
        asm volatile("fence.proxy.async.shared::cta;" ::: "memory");
        asm volatile(
            "cp.async.bulk.global.shared::cta.bulk_group [%0], [%1], %2;"
            :: "l"(gdst), "r"(saddr), "n"(TILE_BYTES) : "memory");
        asm volatile("cp.async.bulk.commit_group;" ::: "memory");
        asm volatile("cp.async.bulk.wait_group 0;" ::: "memory");
    }
}

extern "C" void kernel_launch(void* const* d_in, const int* in_sizes, int n_in,
                              void* d_out, int out_size)
{
    const float* enc   = (const float*)d_in[0];  // (B,S,H)
    const float* ldur  = (const float*)d_in[1];  // (B,S)
    const float* pitch = (const float*)d_in[2];  // (B,S)
    const float* energ = (const float*)d_in[3];  // (B,S)
    const float* pemb  = (const float*)d_in[4];  // (256,H)
    const float* eemb  = (const float*)d_in[5];  // (256,H)

    float* out = (float*)d_out;
    const int main_elems = NB * NL * NH;
    const int write_tail = (out_size >= main_elems + NB) ? 1 : 0;

    prep_kernel<<<NB, NS>>>(ldur, pitch, energ,
                            (const float4*)pemb, (const float4*)eemb,
                            out + main_elems, write_tail);

    dim3 grid(NL / TR, NB);      // 125 x 16 = 2000 blocks
    dim3 block(96, 4);
    expand_kernel<<<grid, block>>>((const float4*)enc, (float4*)out);
}